// round 11
// baseline (speedup 1.0000x reference)
#include <cuda_runtime.h>
#include <math.h>

#define NTOK 2048
#define DMODEL 768
#define NHEAD 12
#define HDIM 64
#define SEQ 512
#define NBATCH 4
#define FFDIM 3072
#define VOCAB 50257
#define NLAYER 4
#define K1W 614
#define K2W 154
#define KC 768   // Eigen kc (Grace L1=64KB): single block for K<=1020, 4x768 for K=3072

__device__ float g_x[NTOK*DMODEL];
__device__ float g_h[NTOK*DMODEL];
__device__ float g_q[NTOK*DMODEL];
__device__ float g_k[NTOK*DMODEL];
__device__ float g_v[NTOK*DMODEL];
__device__ float g_y[NTOK*DMODEL];
__device__ float g_z[NTOK*DMODEL];
__device__ float g_att[(size_t)NBATCH*NHEAD*SEQ*SEQ];
__device__ float g_z1[NTOK*FFDIM];

// XLA:CPU GenerateVF32Exp (Cephes): clamp, floor(fma(x,log2e,0.5)),
// UNFUSED C1/C2 subtraction, fused Horner, 2^n via exponent bits.
__device__ __forceinline__ float xla_expf(float input){
    float x = fminf(input, 88.3762626647950f);
    x = fmaxf(x, -88.3762626647949f);
    float fx = floorf(__fmaf_rn(x, 1.44269504088896341f, 0.5f));
    float tmp = __fmul_rn(0.693359375f, fx);
    float z   = __fmul_rn(-2.12194440e-4f, fx);
    x = __fsub_rn(x, tmp);
    x = __fsub_rn(x, z);
    float z2 = __fmul_rn(x, x);
    float y = __fmaf_rn(1.9875691500e-4f, x, 1.3981999507e-3f);
    y = __fmaf_rn(y, x, 8.3334519073e-3f);
    y = __fmaf_rn(y, x, 4.1665795894e-2f);
    y = __fmaf_rn(y, x, 1.6666665459e-1f);
    y = __fmaf_rn(y, x, 5.0000001201e-1f);
    y = __fmaf_rn(y, z2, x);
    y = __fadd_rn(y, 1.0f);
    int n = (int)fx;
    return __fmul_rn(y, __uint_as_float((unsigned)((n + 127) << 23)));
}

// XLA erf expansion (Eigen-derived rational): clamp +-4, x*P(x2)/Q(x2)
__device__ __forceinline__ float xla_erff(float v){
    float x = fmaxf(-4.0f, fminf(v, 4.0f));
    float x2 = __fmul_rn(x, x);
    float a = __fmaf_rn(x2, -2.72614225801306e-10f, 2.77068142495902e-08f);
    a = __fmaf_rn(x2, a, -2.10102402082508e-06f);
    a = __fmaf_rn(x2, a, -5.69250639462346e-05f);
    a = __fmaf_rn(x2, a, -7.34990630326855e-04f);
    a = __fmaf_rn(x2, a, -2.95459980854025e-03f);
    a = __fmaf_rn(x2, a, -1.60960333262415e-02f);
    a = __fmul_rn(x, a);
    float b = __fmaf_rn(x2, -1.45660718464996e-05f, -2.13374055278905e-04f);
    b = __fmaf_rn(x2, b, -1.68282697438203e-03f);
    b = __fmaf_rn(x2, b, -7.37332916720468e-03f);
    b = __fmaf_rn(x2, b, -1.42647390514189e-02f);
    return __fdiv_rn(a, b);
}

// jax.nn.gelu(approximate=False): (x * (erf(x/sqrt2) + 1)) / 2
__device__ __forceinline__ float gelu_ref(float v){
    float t = xla_erff(__fdiv_rn(v, 1.4142135623730951f));
    float u = __fmul_rn(v, __fadd_rn(t, 1.0f));
    return __fdiv_rn(u, 2.0f);
}

__global__ void embed_kernel(const int* __restrict__ idx, const float* __restrict__ tok,
                             const float* __restrict__ pos, float* __restrict__ x){
    int i = blockIdx.x*blockDim.x + threadIdx.x;
    if (i < NTOK*DMODEL){
        int row = i / DMODEL, d = i - row*DMODEL, t = row & (SEQ-1);
        x[i] = __fadd_rn(tok[(size_t)idx[row]*DMODEL + d], pos[t*DMODEL + d]);
    }
}

__global__ void __launch_bounds__(256) ln_seq_kernel(const float* __restrict__ X,
    const float* __restrict__ gam, const float* __restrict__ bet, float* __restrict__ out){
    __shared__ float row[DMODEL];
    __shared__ float s_mu, s_inv;
    int r = blockIdx.x, t = threadIdx.x;
    const float* xr = X + (size_t)r*DMODEL;
    row[t]=xr[t]; row[t+256]=xr[t+256]; row[t+512]=xr[t+512];
    __syncthreads();
    if (t==0){
        float s=0.f;
        for (int i=0;i<DMODEL;i++) s=__fadd_rn(s,row[i]);
        s_mu = __fdiv_rn(s, 768.0f);
    }
    __syncthreads();
    float mu = s_mu;
    if (t==0){
        float s2=0.f;
        for (int i=0;i<DMODEL;i++){ float d=__fsub_rn(row[i],mu); s2=__fadd_rn(s2,__fmul_rn(d,d)); }
        s_inv = __fdiv_rn(1.0f, __fsqrt_rn(__fadd_rn(__fdiv_rn(s2,768.0f), 1e-5f)));
    }
    __syncthreads();
    float inv = s_inv;
    float* o = out + (size_t)r*DMODEL;
    for (int i=t;i<DMODEL;i+=256){
        float d=__fsub_rn(row[i],mu);
        o[i]=__fadd_rn(__fmul_rn(__fmul_rn(d,inv),gam[i]),bet[i]);
    }
}

// C[M,N]=A[M,K]*B[N,K]^T ; Eigen chains: fold partials every KC=768 (for K=768
// this is fold-at-end == single ascending chain). epi: (res+acc)+bias
__global__ void __launch_bounds__(256) gemm_nt_kernel(
    const float* __restrict__ A, const float* __restrict__ B,
    const float* __restrict__ bias, const float* __restrict__ res,
    float* __restrict__ C, int M, int N, int K){
    __shared__ float As[8][128];
    __shared__ float Bs[8][128];
    int tid = threadIdx.x;
    int bm = blockIdx.y*128, bn = blockIdx.x*128;
    int tx = tid & 15, ty = tid >> 4;
    int lrow = tid >> 1, lcol = (tid & 1)*4;
    bool aval = (bm+lrow) < M, bval = (bn+lrow) < N;
    const float* Ap = A + (size_t)(bm+lrow)*K + lcol;
    const float* Bp = B + (size_t)(bn+lrow)*K + lcol;
    float blk[8][8], tot[8][8];
#pragma unroll
    for (int i=0;i<8;i++)
#pragma unroll
        for (int j=0;j<8;j++){ blk[i][j]=0.f; tot[i][j]=0.f; }

    for (int k0=0;k0<K;k0+=8){
        float4 a4 = aval ? *(const float4*)(Ap+k0) : make_float4(0,0,0,0);
        float4 b4 = bval ? *(const float4*)(Bp+k0) : make_float4(0,0,0,0);
        As[lcol+0][lrow]=a4.x; As[lcol+1][lrow]=a4.y; As[lcol+2][lrow]=a4.z; As[lcol+3][lrow]=a4.w;
        Bs[lcol+0][lrow]=b4.x; Bs[lcol+1][lrow]=b4.y; Bs[lcol+2][lrow]=b4.z; Bs[lcol+3][lrow]=b4.w;
        __syncthreads();
#pragma unroll
        for (int kk=0;kk<8;kk++){
            float4 a0=*(const float4*)&As[kk][ty*8];
            float4 a1=*(const float4*)&As[kk][ty*8+4];
            float4 b0=*(const float4*)&Bs[kk][tx*8];
            float4 b1=*(const float4*)&Bs[kk][tx*8+4];
            float av[8]={a0.x,a0.y,a0.z,a0.w,a1.x,a1.y,a1.z,a1.w};
            float bv[8]={b0.x,b0.y,b0.z,b0.w,b1.x,b1.y,b1.z,b1.w};
#pragma unroll
            for (int i=0;i<8;i++)
#pragma unroll
                for (int j=0;j<8;j++)
                    blk[i][j]=__fmaf_rn(av[i],bv[j],blk[i][j]);
        }
        __syncthreads();
        int kn = k0 + 8;
        if ((kn % KC) == 0 || kn == K){
#pragma unroll
            for (int i=0;i<8;i++)
#pragma unroll
                for (int j=0;j<8;j++){ tot[i][j]=__fadd_rn(tot[i][j],blk[i][j]); blk[i][j]=0.f; }
        }
    }
#pragma unroll
    for (int i=0;i<8;i++){
        int r = bm + ty*8 + i;
        if (r < M){
#pragma unroll
            for (int j=0;j<8;j++){
                int c = bn + tx*8 + j;
                if (c < N){
                    float vv = tot[i][j];
                    if (res)  vv = __fadd_rn(res[(size_t)r*N+c], vv);
                    if (bias) vv = __fadd_rn(vv, bias[c]);
                    C[(size_t)r*N+c] = vv;
                }
            }
        }
    }
}

// scores: K=64 single ascending chain; *0.125 exact; -inf mask
__global__ void __launch_bounds__(256) attn_scores_kernel(
    const float* __restrict__ Q, const float* __restrict__ Kmat, float* __restrict__ att){
    int jt=blockIdx.x, it=blockIdx.y, bh=blockIdx.z;
    int b=bh/NHEAD, h=bh-b*NHEAD;
    int tid=threadIdx.x, tx=tid&15, ty=tid>>4;
    if (jt > it){
#pragma unroll
        for (int ii=0;ii<4;ii++)
#pragma unroll
            for (int jj=0;jj<4;jj++){
                int i=it*64+ty*4+ii, j=jt*64+tx*4+jj;
                att[((size_t)bh*SEQ+i)*SEQ+j] = -INFINITY;
            }
        return;
    }
    __shared__ float qs[16][64];
    __shared__ float ks[16][64];
    float acc[4][4]={};
    int lr=tid>>2, lc=(tid&3)*4;
    const float* qb = Q    + ((size_t)(b*SEQ+it*64+lr))*DMODEL + h*HDIM;
    const float* kb = Kmat + ((size_t)(b*SEQ+jt*64+lr))*DMODEL + h*HDIM;
    for (int d0=0;d0<HDIM;d0+=16){
        float4 qv=*(const float4*)(qb+d0+lc);
        float4 kv=*(const float4*)(kb+d0+lc);
        qs[lc+0][lr]=qv.x; qs[lc+1][lr]=qv.y; qs[lc+2][lr]=qv.z; qs[lc+3][lr]=qv.w;
        ks[lc+0][lr]=kv.x; ks[lc+1][lr]=kv.y; ks[lc+2][lr]=kv.z; ks[lc+3][lr]=kv.w;
        __syncthreads();
#pragma unroll
        for (int kk=0;kk<16;kk++){
            float4 a=*(const float4*)&qs[kk][ty*4];
            float4 c=*(const float4*)&ks[kk][tx*4];
            float av[4]={a.x,a.y,a.z,a.w}, cv[4]={c.x,c.y,c.z,c.w};
#pragma unroll
            for (int ii=0;ii<4;ii++)
#pragma unroll
                for (int jj=0;jj<4;jj++)
                    acc[ii][jj]=__fmaf_rn(av[ii],cv[jj],acc[ii][jj]);
        }
        __syncthreads();
    }
#pragma unroll
    for (int ii=0;ii<4;ii++)
#pragma unroll
        for (int jj=0;jj<4;jj++){
            int i=it*64+ty*4+ii, j=jt*64+tx*4+jj;
            att[((size_t)bh*SEQ+i)*SEQ+j] = (j<=i) ? __fmul_rn(acc[ii][jj],0.125f) : -INFINITY;
        }
}

// softmax: tree max (order-exact), XLA exp, sequential sum, true division
__global__ void __launch_bounds__(256) softmax_seq_kernel(float* __restrict__ att){
    __shared__ float e[SEQ];
    __shared__ float red[256];
    __shared__ float s_sum;
    int r=blockIdx.x, t=threadIdx.x;
    float* rowp = att + (size_t)r*SEQ;
    float a=rowp[t], b=rowp[t+256];
    red[t]=fmaxf(a,b);
    __syncthreads();
    for (int s=128;s>0;s>>=1){ if (t<s) red[t]=fmaxf(red[t],red[t+s]); __syncthreads(); }
    float m = red[0];
    e[t]     = xla_expf(__fsub_rn(a,m));
    e[t+256] = xla_expf(__fsub_rn(b,m));
    __syncthreads();
    if (t==0){
        float s=0.f;
        for (int i=0;i<SEQ;i++) s=__fadd_rn(s,e[i]);
        s_sum=s;
    }
    __syncthreads();
    float s=s_sum;
    rowp[t]     = __fdiv_rn(e[t],s);
    rowp[t+256] = __fdiv_rn(e[t+256],s);
}

// y = att @ v : K<=512 -> single ascending chain (Eigen: no split for K<=1020)
__global__ void __launch_bounds__(256) attn_av_kernel(
    const float* __restrict__ att, const float* __restrict__ V, float* __restrict__ Y){
    int it=blockIdx.x, bh=blockIdx.y;
    int b=bh/NHEAD, h=bh-b*NHEAD;
    int tid=threadIdx.x, tx=tid&15, ty=tid>>4;
    __shared__ float as_s[16][64];
    __shared__ float vs_s[16][64];
    float acc[4][4]={};
    int ar=tid>>2, ac4=(tid&3)*4;
    int vr=tid>>4, vc4=(tid&15)*4;
    int jmax=(it+1)*64;
    for (int j0=0;j0<jmax;j0+=16){
        float4 av=*(const float4*)(att + ((size_t)bh*SEQ+it*64+ar)*SEQ + j0 + ac4);
        as_s[ac4+0][ar]=av.x; as_s[ac4+1][ar]=av.y; as_s[ac4+2][ar]=av.z; as_s[ac4+3][ar]=av.w;
        float4 vv=*(const float4*)(V + ((size_t)(b*SEQ+j0+vr))*DMODEL + h*HDIM + vc4);
        *(float4*)&vs_s[vr][vc4]=vv;
        __syncthreads();
#pragma unroll
        for (int jj=0;jj<16;jj++){
            float4 a=*(const float4*)&as_s[jj][ty*4];
            float4 c=*(const float4*)&vs_s[jj][tx*4];
            float av2[4]={a.x,a.y,a.z,a.w}, cv[4]={c.x,c.y,c.z,c.w};
#pragma unroll
            for (int ii=0;ii<4;ii++)
#pragma unroll
                for (int dd=0;dd<4;dd++)
                    acc[ii][dd]=__fmaf_rn(av2[ii],cv[dd],acc[ii][dd]);
        }
        __syncthreads();
    }
#pragma unroll
    for (int ii=0;ii<4;ii++)
#pragma unroll
        for (int dd=0;dd<4;dd++)
            Y[((size_t)(b*SEQ+it*64+ty*4+ii))*DMODEL + h*HDIM + tx*4 + dd] = acc[ii][dd];
}

__device__ __forceinline__ unsigned fkey(float f){
    unsigned b=__float_as_uint(f);
    return (b & 0x80000000u) ? ~b : (b | 0x80000000u);
}
__device__ __forceinline__ float fromkey(unsigned u){
    unsigned b=(u & 0x80000000u) ? (u & 0x7fffffffu) : ~u;
    return __uint_as_float(b);
}

template <int ROW, bool GELU, bool RESID>
__global__ void __launch_bounds__(256) kwinners_kernel(
    const float* __restrict__ Z, float* __restrict__ out, int kcount){
    __shared__ float vals[ROW];
    __shared__ unsigned hist[256];
    __shared__ unsigned s_prefix;
    __shared__ int s_k;
    int row=blockIdx.x, tid=threadIdx.x;
    const float* zr = Z + (size_t)row*ROW;
    for (int i=tid;i<ROW;i+=256) vals[i]=zr[i];
    if (tid==0){ s_prefix=0u; s_k=kcount; }
    __syncthreads();
    for (int pass=0;pass<4;pass++){
        int shift=24-8*pass;
        hist[tid]=0u;
        __syncthreads();
        unsigned pfx=s_prefix;
        for (int i=tid;i<ROW;i+=256){
            unsigned u=fkey(vals[i]);
            if (pass==0 || (u>>(shift+8))==pfx) atomicAdd(&hist[(u>>shift)&255u],1u);
        }
        __syncthreads();
        if (tid==0){
            int kk=s_k; unsigned p=pfx;
            for (int bb=255;bb>=0;bb--){
                int c=(int)hist[bb];
                if (kk<=c){ p=(p<<8)|(unsigned)bb; break; }
                kk-=c;
            }
            s_prefix=p; s_k=kk;
        }
        __syncthreads();
    }
    float thr=fromkey(s_prefix);
    float* o = out + (size_t)row*ROW;
    for (int i=tid;i<ROW;i+=256){
        float v=vals[i];
        if (GELU){
            o[i] = (v>=thr) ? gelu_ref(v) : 0.0f;
        } else if (RESID){
            o[i] = __fadd_rn(o[i], (v>=thr)?v:0.0f);
        } else {
            o[i] = (v>=thr)?v:0.0f;
        }
    }
}

__global__ void copy_kernel(const float* __restrict__ src, float* __restrict__ dst, int n){
    int i=blockIdx.x*blockDim.x+threadIdx.x;
    if (i<n) dst[i]=src[i];
}

extern "C" void kernel_launch(void* const* d_in, const int* in_sizes, int n_in,
                              void* d_out, int out_size){
    const int*   idx  = (const int*)  d_in[0];
    const float* tok  = (const float*)d_in[1];
    const float* pos  = (const float*)d_in[2];
    const float* ln1s = (const float*)d_in[3];
    const float* ln1b = (const float*)d_in[4];
    const float* Wq   = (const float*)d_in[5];
    const float* bq   = (const float*)d_in[6];
    const float* Wk   = (const float*)d_in[7];
    const float* bk   = (const float*)d_in[8];
    const float* Wv   = (const float*)d_in[9];
    const float* bv   = (const float*)d_in[10];
    const float* Wp   = (const float*)d_in[11];
    const float* bp   = (const float*)d_in[12];
    const float* ln2s = (const float*)d_in[13];
    const float* ln2b = (const float*)d_in[14];
    const float* W1   = (const float*)d_in[15];
    const float* b1   = (const float*)d_in[16];
    const float* W2   = (const float*)d_in[17];
    const float* b2   = (const float*)d_in[18];
    const float* lnfs = (const float*)d_in[19];
    const float* lnfb = (const float*)d_in[20];
    const float* headW= (const float*)d_in[21];
    float* out = (float*)d_out;

    float *x,*h,*q,*k,*v,*y,*z,*att,*z1;
    cudaGetSymbolAddress((void**)&x,g_x);
    cudaGetSymbolAddress((void**)&h,g_h);
    cudaGetSymbolAddress((void**)&q,g_q);
    cudaGetSymbolAddress((void**)&k,g_k);
    cudaGetSymbolAddress((void**)&v,g_v);
    cudaGetSymbolAddress((void**)&y,g_y);
    cudaGetSymbolAddress((void**)&z,g_z);
    cudaGetSymbolAddress((void**)&att,g_att);
    cudaGetSymbolAddress((void**)&z1,g_z1);

    embed_kernel<<<(NTOK*DMODEL+255)/256,256>>>(idx,tok,pos,x);

    dim3 gD(DMODEL/128, NTOK/128);
    dim3 gF(FFDIM/128, NTOK/128);
    dim3 gS(SEQ/64, SEQ/64, NBATCH*NHEAD);
    dim3 gA(SEQ/64, NBATCH*NHEAD);

    for (int l=0;l<NLAYER;l++){
        size_t wo  = (size_t)l*DMODEL*DMODEL;
        size_t wo1 = (size_t)l*FFDIM*DMODEL;
        ln_seq_kernel<<<NTOK,256>>>(x, ln1s+l*DMODEL, ln1b+l*DMODEL, h);
        gemm_nt_kernel<<<gD,256>>>(h, Wq+wo, bq+l*DMODEL, nullptr, q, NTOK, DMODEL, DMODEL);
        gemm_nt_kernel<<<gD,256>>>(h, Wk+wo, bk+l*DMODEL, nullptr, k, NTOK, DMODEL, DMODEL);
        gemm_nt_kernel<<<gD,256>>>(h, Wv+wo, bv+l*DMODEL, nullptr, v, NTOK, DMODEL, DMODEL);
        attn_scores_kernel<<<gS,256>>>(q, k, att);
        softmax_seq_kernel<<<NBATCH*NHEAD*SEQ,256>>>(att);
        attn_av_kernel<<<gA,256>>>(att, v, y);
        gemm_nt_kernel<<<gD,256>>>(y, Wp+wo, bp+l*DMODEL, x, x, NTOK, DMODEL, DMODEL);
        ln_seq_kernel<<<NTOK,256>>>(x, ln2s+l*DMODEL, ln2b+l*DMODEL, h);
        gemm_nt_kernel<<<gF,256>>>(h, W1+wo1, b1+l*FFDIM, nullptr, z1, NTOK, FFDIM, DMODEL);
        kwinners_kernel<FFDIM,true,false><<<NTOK,256>>>(z1, z1, K1W);
        gemm_nt_kernel<<<gD,256>>>(z1, W2+wo1, b2+l*DMODEL, nullptr, h, NTOK, DMODEL, FFDIM);
        kwinners_kernel<DMODEL,false,true><<<NTOK,256>>>(h, x, K2W);
    }

    ln_seq_kernel<<<NTOK,256>>>(x, lnfs, lnfb, z);
    dim3 gH((VOCAB+127)/128, NTOK/128);
    gemm_nt_kernel<<<gH,256>>>(z, headW, nullptr, nullptr, out, NTOK, VOCAB, DMODEL);

    size_t zoff = (size_t)NTOK*VOCAB;
    if ((size_t)out_size >= zoff + (size_t)NTOK*DMODEL)
        copy_kernel<<<(NTOK*DMODEL+255)/256,256>>>(z, out+zoff, NTOK*DMODEL);
}

// round 13
// speedup vs baseline: 1.2497x; 1.2497x over previous
#include <cuda_runtime.h>
#include <math.h>

#define NTOK 2048
#define DMODEL 768
#define NHEAD 12
#define HDIM 64
#define SEQ 512
#define NBATCH 4
#define FFDIM 3072
#define VOCAB 50257
#define NLAYER 4
#define K1W 614
#define K2W 154
#define KC 768   // Eigen kc (Grace L1=64KB): single chain K<=1020; 4x768 folds for K=3072

__device__ float g_x[NTOK*DMODEL];
__device__ float g_h[NTOK*DMODEL];
__device__ float g_q[NTOK*DMODEL];
__device__ float g_k[NTOK*DMODEL];
__device__ float g_v[NTOK*DMODEL];
__device__ float g_y[NTOK*DMODEL];
__device__ float g_z[NTOK*DMODEL];
__device__ float g_att[(size_t)NBATCH*NHEAD*SEQ*SEQ];
__device__ float g_z1[NTOK*FFDIM];

// XLA:CPU GenerateVF32Exp (Cephes) — DO NOT TOUCH (bit-matched to reference)
__device__ __forceinline__ float xla_expf(float input){
    float x = fminf(input, 88.3762626647950f);
    x = fmaxf(x, -88.3762626647949f);
    float fx = floorf(__fmaf_rn(x, 1.44269504088896341f, 0.5f));
    float tmp = __fmul_rn(0.693359375f, fx);
    float z   = __fmul_rn(-2.12194440e-4f, fx);
    x = __fsub_rn(x, tmp);
    x = __fsub_rn(x, z);
    float z2 = __fmul_rn(x, x);
    float y = __fmaf_rn(1.9875691500e-4f, x, 1.3981999507e-3f);
    y = __fmaf_rn(y, x, 8.3334519073e-3f);
    y = __fmaf_rn(y, x, 4.1665795894e-2f);
    y = __fmaf_rn(y, x, 1.6666665459e-1f);
    y = __fmaf_rn(y, x, 5.0000001201e-1f);
    y = __fmaf_rn(y, z2, x);
    y = __fadd_rn(y, 1.0f);
    int n = (int)fx;
    return __fmul_rn(y, __uint_as_float((unsigned)((n + 127) << 23)));
}

// XLA erf rational — DO NOT TOUCH (bit-matched to reference)
__device__ __forceinline__ float xla_erff(float v){
    float x = fmaxf(-4.0f, fminf(v, 4.0f));
    float x2 = __fmul_rn(x, x);
    float a = __fmaf_rn(x2, -2.72614225801306e-10f, 2.77068142495902e-08f);
    a = __fmaf_rn(x2, a, -2.10102402082508e-06f);
    a = __fmaf_rn(x2, a, -5.69250639462346e-05f);
    a = __fmaf_rn(x2, a, -7.34990630326855e-04f);
    a = __fmaf_rn(x2, a, -2.95459980854025e-03f);
    a = __fmaf_rn(x2, a, -1.60960333262415e-02f);
    a = __fmul_rn(x, a);
    float b = __fmaf_rn(x2, -1.45660718464996e-05f, -2.13374055278905e-04f);
    b = __fmaf_rn(x2, b, -1.68282697438203e-03f);
    b = __fmaf_rn(x2, b, -7.37332916720468e-03f);
    b = __fmaf_rn(x2, b, -1.42647390514189e-02f);
    return __fdiv_rn(a, b);
}

__device__ __forceinline__ float gelu_ref(float v){
    float t = xla_erff(__fdiv_rn(v, 1.4142135623730951f));
    float u = __fmul_rn(v, __fadd_rn(t, 1.0f));
    return __fdiv_rn(u, 2.0f);
}

__global__ void embed_kernel(const int* __restrict__ idx, const float* __restrict__ tok,
                             const float* __restrict__ pos, float* __restrict__ x){
    int i = blockIdx.x*blockDim.x + threadIdx.x;
    if (i < NTOK*DMODEL){
        int row = i / DMODEL, d = i - row*DMODEL, t = row & (SEQ-1);
        x[i] = __fadd_rn(tok[(size_t)idx[row]*DMODEL + d], pos[t*DMODEL + d]);
    }
}

__global__ void __launch_bounds__(256) ln_seq_kernel(const float* __restrict__ X,
    const float* __restrict__ gam, const float* __restrict__ bet, float* __restrict__ out){
    __shared__ float row[DMODEL];
    __shared__ float s_mu, s_inv;
    int r = blockIdx.x, t = threadIdx.x;
    const float* xr = X + (size_t)r*DMODEL;
    row[t]=xr[t]; row[t+256]=xr[t+256]; row[t+512]=xr[t+512];
    __syncthreads();
    if (t==0){
        float s=0.f;
        for (int i=0;i<DMODEL;i++) s=__fadd_rn(s,row[i]);
        s_mu = __fdiv_rn(s, 768.0f);
    }
    __syncthreads();
    float mu = s_mu;
    if (t==0){
        float s2=0.f;
        for (int i=0;i<DMODEL;i++){ float d=__fsub_rn(row[i],mu); s2=__fadd_rn(s2,__fmul_rn(d,d)); }
        s_inv = __fdiv_rn(1.0f, __fsqrt_rn(__fadd_rn(__fdiv_rn(s2,768.0f), 1e-5f)));
    }
    __syncthreads();
    float inv = s_inv;
    float* o = out + (size_t)r*DMODEL;
    for (int i=t;i<DMODEL;i+=256){
        float d=__fsub_rn(row[i],mu);
        o[i]=__fadd_rn(__fmul_rn(__fmul_rn(d,inv),gam[i]),bet[i]);
    }
}

// ---------------------------------------------------------------------------
// C[M,N]=A[M,K]*B[N,K]^T ; Eigen chains: ascending-k fused-FMA per output,
// partials folded every KC=768 (fold-at-end == single chain for K=768).
// Tile 128(M) x 64(N), microtile 8x4 -> 32 accumulators/thread (~2 blocks/SM).
// Per-output FP chain identical to the R8/R11 passing kernel.
// ---------------------------------------------------------------------------
__global__ void __launch_bounds__(256) gemm_nt_kernel(
    const float* __restrict__ A, const float* __restrict__ B,
    const float* __restrict__ bias, const float* __restrict__ res,
    float* __restrict__ C, int M, int N, int K){
    __shared__ float As[8][128];
    __shared__ float Bs[8][64];
    int tid = threadIdx.x;
    int bm = blockIdx.y*128, bn = blockIdx.x*64;
    int tx = tid & 15, ty = tid >> 4;
    int lrow = tid >> 1, lcol = (tid & 1)*4;       // A: 128 rows x 8 k, float4
    int lrB = tid >> 2, lcB = (tid & 3)*2;         // B: 64 rows x 8 k, float2
    bool aval = (bm+lrow) < M;
    bool bval = (bn+lrB) < N;
    const float* Ap = A + (size_t)(bm+lrow)*K + lcol;
    const float* Bp = B + (size_t)(bn+lrB)*K + lcB;
    float blk[8][4], tot[8][4];
#pragma unroll
    for (int i=0;i<8;i++)
#pragma unroll
        for (int j=0;j<4;j++){ blk[i][j]=0.f; tot[i][j]=0.f; }

    for (int k0=0;k0<K;k0+=8){
        float4 a4 = aval ? *(const float4*)(Ap+k0) : make_float4(0,0,0,0);
        float2 b2 = bval ? *(const float2*)(Bp+k0) : make_float2(0,0);
        As[lcol+0][lrow]=a4.x; As[lcol+1][lrow]=a4.y; As[lcol+2][lrow]=a4.z; As[lcol+3][lrow]=a4.w;
        Bs[lcB+0][lrB]=b2.x;  Bs[lcB+1][lrB]=b2.y;
        __syncthreads();
#pragma unroll
        for (int kk=0;kk<8;kk++){
            float4 a0=*(const float4*)&As[kk][ty*8];
            float4 a1=*(const float4*)&As[kk][ty*8+4];
            float4 b0=*(const float4*)&Bs[kk][tx*4];
            float av[8]={a0.x,a0.y,a0.z,a0.w,a1.x,a1.y,a1.z,a1.w};
            float bv[4]={b0.x,b0.y,b0.z,b0.w};
#pragma unroll
            for (int i=0;i<8;i++)
#pragma unroll
                for (int j=0;j<4;j++)
                    blk[i][j]=__fmaf_rn(av[i],bv[j],blk[i][j]);
        }
        __syncthreads();
        int kn = k0 + 8;
        if ((kn % KC) == 0 || kn == K){
#pragma unroll
            for (int i=0;i<8;i++)
#pragma unroll
                for (int j=0;j<4;j++){ tot[i][j]=__fadd_rn(tot[i][j],blk[i][j]); blk[i][j]=0.f; }
        }
    }
#pragma unroll
    for (int i=0;i<8;i++){
        int r = bm + ty*8 + i;
        if (r < M){
#pragma unroll
            for (int j=0;j<4;j++){
                int c = bn + tx*4 + j;
                if (c < N){
                    float vv = tot[i][j];
                    if (res)  vv = __fadd_rn(res[(size_t)r*N+c], vv);
                    if (bias) vv = __fadd_rn(vv, bias[c]);
                    C[(size_t)r*N+c] = vv;
                }
            }
        }
    }
}

// scores: K=64 single ascending chain; *0.125 exact; -inf mask
__global__ void __launch_bounds__(256) attn_scores_kernel(
    const float* __restrict__ Q, const float* __restrict__ Kmat, float* __restrict__ att){
    int jt=blockIdx.x, it=blockIdx.y, bh=blockIdx.z;
    int b=bh/NHEAD, h=bh-b*NHEAD;
    int tid=threadIdx.x, tx=tid&15, ty=tid>>4;
    if (jt > it){
#pragma unroll
        for (int ii=0;ii<4;ii++)
#pragma unroll
            for (int jj=0;jj<4;jj++){
                int i=it*64+ty*4+ii, j=jt*64+tx*4+jj;
                att[((size_t)bh*SEQ+i)*SEQ+j] = -INFINITY;
            }
        return;
    }
    __shared__ float qs[16][64];
    __shared__ float ks[16][64];
    float acc[4][4]={};
    int lr=tid>>2, lc=(tid&3)*4;
    const float* qb = Q    + ((size_t)(b*SEQ+it*64+lr))*DMODEL + h*HDIM;
    const float* kb = Kmat + ((size_t)(b*SEQ+jt*64+lr))*DMODEL + h*HDIM;
    for (int d0=0;d0<HDIM;d0+=16){
        float4 qv=*(const float4*)(qb+d0+lc);
        float4 kv=*(const float4*)(kb+d0+lc);
        qs[lc+0][lr]=qv.x; qs[lc+1][lr]=qv.y; qs[lc+2][lr]=qv.z; qs[lc+3][lr]=qv.w;
        ks[lc+0][lr]=kv.x; ks[lc+1][lr]=kv.y; ks[lc+2][lr]=kv.z; ks[lc+3][lr]=kv.w;
        __syncthreads();
#pragma unroll
        for (int kk=0;kk<16;kk++){
            float4 a=*(const float4*)&qs[kk][ty*4];
            float4 c=*(const float4*)&ks[kk][tx*4];
            float av[4]={a.x,a.y,a.z,a.w}, cv[4]={c.x,c.y,c.z,c.w};
#pragma unroll
            for (int ii=0;ii<4;ii++)
#pragma unroll
                for (int jj=0;jj<4;jj++)
                    acc[ii][jj]=__fmaf_rn(av[ii],cv[jj],acc[ii][jj]);
        }
        __syncthreads();
    }
#pragma unroll
    for (int ii=0;ii<4;ii++)
#pragma unroll
        for (int jj=0;jj<4;jj++){
            int i=it*64+ty*4+ii, j=jt*64+tx*4+jj;
            att[((size_t)bh*SEQ+i)*SEQ+j] = (j<=i) ? __fmul_rn(acc[ii][jj],0.125f) : -INFINITY;
        }
}

// softmax: tree max (order-exact), XLA exp, sequential sum, true division
__global__ void __launch_bounds__(256) softmax_seq_kernel(float* __restrict__ att){
    __shared__ float e[SEQ];
    __shared__ float red[256];
    __shared__ float s_sum;
    int r=blockIdx.x, t=threadIdx.x;
    float* rowp = att + (size_t)r*SEQ;
    float a=rowp[t], b=rowp[t+256];
    red[t]=fmaxf(a,b);
    __syncthreads();
    for (int s=128;s>0;s>>=1){ if (t<s) red[t]=fmaxf(red[t],red[t+s]); __syncthreads(); }
    float m = red[0];
    e[t]     = xla_expf(__fsub_rn(a,m));
    e[t+256] = xla_expf(__fsub_rn(b,m));
    __syncthreads();
    if (t==0){
        float s=0.f;
        for (int i=0;i<SEQ;i++) s=__fadd_rn(s,e[i]);
        s_sum=s;
    }
    __syncthreads();
    float s=s_sum;
    rowp[t]     = __fdiv_rn(e[t],s);
    rowp[t+256] = __fdiv_rn(e[t+256],s);
}

// y = att @ v : K<=512 -> single ascending chain
__global__ void __launch_bounds__(256) attn_av_kernel(
    const float* __restrict__ att, const float* __restrict__ V, float* __restrict__ Y){
    int it=blockIdx.x, bh=blockIdx.y;
    int b=bh/NHEAD, h=bh-b*NHEAD;
    int tid=threadIdx.x, tx=tid&15, ty=tid>>4;
    __shared__ float as_s[16][64];
    __shared__ float vs_s[16][64];
    float acc[4][4]={};
    int ar=tid>>2, ac4=(tid&3)*4;
    int vr=tid>>4, vc4=(tid&15)*4;
    int jmax=(it+1)*64;
    for (int j0=0;j0<jmax;j0+=16){
        float4 av=*(const float4*)(att + ((size_t)bh*SEQ+it*64+ar)*SEQ + j0 + ac4);
        as_s[ac4+0][ar]=av.x; as_s[ac4+1][ar]=av.y; as_s[ac4+2][ar]=av.z; as_s[ac4+3][ar]=av.w;
        float4 vv=*(const float4*)(V + ((size_t)(b*SEQ+j0+vr))*DMODEL + h*HDIM + vc4);
        *(float4*)&vs_s[vr][vc4]=vv;
        __syncthreads();
#pragma unroll
        for (int jj=0;jj<16;jj++){
            float4 a=*(const float4*)&as_s[jj][ty*4];
            float4 c=*(const float4*)&vs_s[jj][tx*4];
            float av2[4]={a.x,a.y,a.z,a.w}, cv[4]={c.x,c.y,c.z,c.w};
#pragma unroll
            for (int ii=0;ii<4;ii++)
#pragma unroll
                for (int dd=0;dd<4;dd++)
                    acc[ii][dd]=__fmaf_rn(av2[ii],cv[dd],acc[ii][dd]);
        }
        __syncthreads();
    }
#pragma unroll
    for (int ii=0;ii<4;ii++)
#pragma unroll
        for (int dd=0;dd<4;dd++)
            Y[((size_t)(b*SEQ+it*64+ty*4+ii))*DMODEL + h*HDIM + tx*4 + dd] = acc[ii][dd];
}

__device__ __forceinline__ unsigned fkey(float f){
    unsigned b=__float_as_uint(f);
    return (b & 0x80000000u) ? ~b : (b | 0x80000000u);
}
__device__ __forceinline__ float fromkey(unsigned u){
    unsigned b=(u & 0x80000000u) ? (u & 0x7fffffffu) : ~u;
    return __uint_as_float(b);
}

template <int ROW, bool GELU, bool RESID>
__global__ void __launch_bounds__(256) kwinners_kernel(
    const float* __restrict__ Z, float* __restrict__ out, int kcount){
    __shared__ float vals[ROW];
    __shared__ unsigned hist[256];
    __shared__ unsigned s_prefix;
    __shared__ int s_k;
    int row=blockIdx.x, tid=threadIdx.x;
    const float* zr = Z + (size_t)row*ROW;
    for (int i=tid;i<ROW;i+=256) vals[i]=zr[i];
    if (tid==0){ s_prefix=0u; s_k=kcount; }
    __syncthreads();
    for (int pass=0;pass<4;pass++){
        int shift=24-8*pass;
        hist[tid]=0u;
        __syncthreads();
        unsigned pfx=s_prefix;
        for (int i=tid;i<ROW;i+=256){
            unsigned u=fkey(vals[i]);
            if (pass==0 || (u>>(shift+8))==pfx) atomicAdd(&hist[(u>>shift)&255u],1u);
        }
        __syncthreads();
        if (tid==0){
            int kk=s_k; unsigned p=pfx;
            for (int bb=255;bb>=0;bb--){
                int c=(int)hist[bb];
                if (kk<=c){ p=(p<<8)|(unsigned)bb; break; }
                kk-=c;
            }
            s_prefix=p; s_k=kk;
        }
        __syncthreads();
    }
    float thr=fromkey(s_prefix);
    float* o = out + (size_t)row*ROW;
    for (int i=tid;i<ROW;i+=256){
        float v=vals[i];
        if (GELU){
            o[i] = (v>=thr) ? gelu_ref(v) : 0.0f;
        } else if (RESID){
            o[i] = __fadd_rn(o[i], (v>=thr)?v:0.0f);
        } else {
            o[i] = (v>=thr)?v:0.0f;
        }
    }
}

__global__ void copy_kernel(const float* __restrict__ src, float* __restrict__ dst, int n){
    int i=blockIdx.x*blockDim.x+threadIdx.x;
    if (i<n) dst[i]=src[i];
}

extern "C" void kernel_launch(void* const* d_in, const int* in_sizes, int n_in,
                              void* d_out, int out_size){
    const int*   idx  = (const int*)  d_in[0];
    const float* tok  = (const float*)d_in[1];
    const float* pos  = (const float*)d_in[2];
    const float* ln1s = (const float*)d_in[3];
    const float* ln1b = (const float*)d_in[4];
    const float* Wq   = (const float*)d_in[5];
    const float* bq   = (const float*)d_in[6];
    const float* Wk   = (const float*)d_in[7];
    const float* bk   = (const float*)d_in[8];
    const float* Wv   = (const float*)d_in[9];
    const float* bv   = (const float*)d_in[10];
    const float* Wp   = (const float*)d_in[11];
    const float* bp   = (const float*)d_in[12];
    const float* ln2s = (const float*)d_in[13];
    const float* ln2b = (const float*)d_in[14];
    const float* W1   = (const float*)d_in[15];
    const float* b1   = (const float*)d_in[16];
    const float* W2   = (const float*)d_in[17];
    const float* b2   = (const float*)d_in[18];
    const float* lnfs = (const float*)d_in[19];
    const float* lnfb = (const float*)d_in[20];
    const float* headW= (const float*)d_in[21];
    float* out = (float*)d_out;

    float *x,*h,*q,*k,*v,*y,*z,*att,*z1;
    cudaGetSymbolAddress((void**)&x,g_x);
    cudaGetSymbolAddress((void**)&h,g_h);
    cudaGetSymbolAddress((void**)&q,g_q);
    cudaGetSymbolAddress((void**)&k,g_k);
    cudaGetSymbolAddress((void**)&v,g_v);
    cudaGetSymbolAddress((void**)&y,g_y);
    cudaGetSymbolAddress((void**)&z,g_z);
    cudaGetSymbolAddress((void**)&att,g_att);
    cudaGetSymbolAddress((void**)&z1,g_z1);

    embed_kernel<<<(NTOK*DMODEL+255)/256,256>>>(idx,tok,pos,x);

    dim3 gD(DMODEL/64, NTOK/128);             // (12,16)
    dim3 gF(FFDIM/64, NTOK/128);              // (48,16)
    dim3 gS(SEQ/64, SEQ/64, NBATCH*NHEAD);
    dim3 gA(SEQ/64, NBATCH*NHEAD);

    for (int l=0;l<NLAYER;l++){
        size_t wo  = (size_t)l*DMODEL*DMODEL;
        size_t wo1 = (size_t)l*FFDIM*DMODEL;
        ln_seq_kernel<<<NTOK,256>>>(x, ln1s+l*DMODEL, ln1b+l*DMODEL, h);
        gemm_nt_kernel<<<gD,256>>>(h, Wq+wo, bq+l*DMODEL, nullptr, q, NTOK, DMODEL, DMODEL);
        gemm_nt_kernel<<<gD,256>>>(h, Wk+wo, bk+l*DMODEL, nullptr, k, NTOK, DMODEL, DMODEL);
        gemm_nt_kernel<<<gD,256>>>(h, Wv+wo, bv+l*DMODEL, nullptr, v, NTOK, DMODEL, DMODEL);
        attn_scores_kernel<<<gS,256>>>(q, k, att);
        softmax_seq_kernel<<<NBATCH*NHEAD*SEQ,256>>>(att);
        attn_av_kernel<<<gA,256>>>(att, v, y);
        gemm_nt_kernel<<<gD,256>>>(y, Wp+wo, bp+l*DMODEL, x, x, NTOK, DMODEL, DMODEL);
        ln_seq_kernel<<<NTOK,256>>>(x, ln2s+l*DMODEL, ln2b+l*DMODEL, h);
        gemm_nt_kernel<<<gF,256>>>(h, W1+wo1, b1+l*FFDIM, nullptr, z1, NTOK, FFDIM, DMODEL);
        kwinners_kernel<FFDIM,true,false><<<NTOK,256>>>(z1, z1, K1W);
        gemm_nt_kernel<<<gD,256>>>(z1, W2+wo1, b2+l*DMODEL, nullptr, h, NTOK, DMODEL, FFDIM);
        kwinners_kernel<DMODEL,false,true><<<NTOK,256>>>(h, x, K2W);
    }

    ln_seq_kernel<<<NTOK,256>>>(x, lnfs, lnfb, z);
    dim3 gH((VOCAB+63)/64, NTOK/128);         // (786,16)
    gemm_nt_kernel<<<gH,256>>>(z, headW, nullptr, nullptr, out, NTOK, VOCAB, DMODEL);

    size_t zoff = (size_t)NTOK*VOCAB;
    if ((size_t)out_size >= zoff + (size_t)NTOK*DMODEL)
        copy_kernel<<<(NTOK*DMODEL+255)/256,256>>>(z, out+zoff, NTOK*DMODEL);
}

// round 14
// speedup vs baseline: 1.5061x; 1.2051x over previous
#include <cuda_runtime.h>
#include <math.h>

#define NTOK 2048
#define DMODEL 768
#define NHEAD 12
#define HDIM 64
#define SEQ 512
#define NBATCH 4
#define FFDIM 3072
#define VOCAB 50257
#define NLAYER 4
#define K1W 614
#define K2W 154
#define KC 768   // Eigen kc (Grace L1=64KB): single chain K<=1020; 4x768 folds for K=3072

__device__ float g_x[NTOK*DMODEL];
__device__ float g_h[NTOK*DMODEL];
__device__ float g_q[NTOK*DMODEL];
__device__ float g_k[NTOK*DMODEL];
__device__ float g_v[NTOK*DMODEL];
__device__ float g_y[NTOK*DMODEL];
__device__ float g_z[NTOK*DMODEL];
__device__ float g_att[(size_t)NBATCH*NHEAD*SEQ*SEQ];
__device__ float g_z1[NTOK*FFDIM];

// XLA:CPU GenerateVF32Exp (Cephes) — DO NOT TOUCH (bit-matched to reference)
__device__ __forceinline__ float xla_expf(float input){
    float x = fminf(input, 88.3762626647950f);
    x = fmaxf(x, -88.3762626647949f);
    float fx = floorf(__fmaf_rn(x, 1.44269504088896341f, 0.5f));
    float tmp = __fmul_rn(0.693359375f, fx);
    float z   = __fmul_rn(-2.12194440e-4f, fx);
    x = __fsub_rn(x, tmp);
    x = __fsub_rn(x, z);
    float z2 = __fmul_rn(x, x);
    float y = __fmaf_rn(1.9875691500e-4f, x, 1.3981999507e-3f);
    y = __fmaf_rn(y, x, 8.3334519073e-3f);
    y = __fmaf_rn(y, x, 4.1665795894e-2f);
    y = __fmaf_rn(y, x, 1.6666665459e-1f);
    y = __fmaf_rn(y, x, 5.0000001201e-1f);
    y = __fmaf_rn(y, z2, x);
    y = __fadd_rn(y, 1.0f);
    int n = (int)fx;
    return __fmul_rn(y, __uint_as_float((unsigned)((n + 127) << 23)));
}

// XLA erf rational — DO NOT TOUCH (bit-matched to reference)
__device__ __forceinline__ float xla_erff(float v){
    float x = fmaxf(-4.0f, fminf(v, 4.0f));
    float x2 = __fmul_rn(x, x);
    float a = __fmaf_rn(x2, -2.72614225801306e-10f, 2.77068142495902e-08f);
    a = __fmaf_rn(x2, a, -2.10102402082508e-06f);
    a = __fmaf_rn(x2, a, -5.69250639462346e-05f);
    a = __fmaf_rn(x2, a, -7.34990630326855e-04f);
    a = __fmaf_rn(x2, a, -2.95459980854025e-03f);
    a = __fmaf_rn(x2, a, -1.60960333262415e-02f);
    a = __fmul_rn(x, a);
    float b = __fmaf_rn(x2, -1.45660718464996e-05f, -2.13374055278905e-04f);
    b = __fmaf_rn(x2, b, -1.68282697438203e-03f);
    b = __fmaf_rn(x2, b, -7.37332916720468e-03f);
    b = __fmaf_rn(x2, b, -1.42647390514189e-02f);
    return __fdiv_rn(a, b);
}

__device__ __forceinline__ float gelu_ref(float v){
    float t = xla_erff(__fdiv_rn(v, 1.4142135623730951f));
    float u = __fmul_rn(v, __fadd_rn(t, 1.0f));
    return __fdiv_rn(u, 2.0f);
}

__global__ void embed_kernel(const int* __restrict__ idx, const float* __restrict__ tok,
                             const float* __restrict__ pos, float* __restrict__ x){
    int i = blockIdx.x*blockDim.x + threadIdx.x;
    if (i < NTOK*DMODEL){
        int row = i / DMODEL, d = i - row*DMODEL, t = row & (SEQ-1);
        x[i] = __fadd_rn(tok[(size_t)idx[row]*DMODEL + d], pos[t*DMODEL + d]);
    }
}

__global__ void __launch_bounds__(256) ln_seq_kernel(const float* __restrict__ X,
    const float* __restrict__ gam, const float* __restrict__ bet, float* __restrict__ out){
    __shared__ float row[DMODEL];
    __shared__ float s_mu, s_inv;
    int r = blockIdx.x, t = threadIdx.x;
    const float* xr = X + (size_t)r*DMODEL;
    row[t]=xr[t]; row[t+256]=xr[t+256]; row[t+512]=xr[t+512];
    __syncthreads();
    if (t==0){
        float s=0.f;
        for (int i=0;i<DMODEL;i++) s=__fadd_rn(s,row[i]);
        s_mu = __fdiv_rn(s, 768.0f);
    }
    __syncthreads();
    float mu = s_mu;
    if (t==0){
        float s2=0.f;
        for (int i=0;i<DMODEL;i++){ float d=__fsub_rn(row[i],mu); s2=__fadd_rn(s2,__fmul_rn(d,d)); }
        s_inv = __fdiv_rn(1.0f, __fsqrt_rn(__fadd_rn(__fdiv_rn(s2,768.0f), 1e-5f)));
    }
    __syncthreads();
    float inv = s_inv;
    float* o = out + (size_t)r*DMODEL;
    for (int i=t;i<DMODEL;i+=256){
        float d=__fsub_rn(row[i],mu);
        o[i]=__fadd_rn(__fmul_rn(__fmul_rn(d,inv),gam[i]),bet[i]);
    }
}

// ---------------------------------------------------------------------------
// C[M,N]=A[M,K]*B[N,K]^T ; per-output ascending-k fused-FMA chain with Eigen
// KC=768 partial folds — FP order identical to the R11/R13 passing kernels.
// Tile 128(M) x 64(N), microtile 8x4. k-slab 16, double-buffered smem,
// one __syncthreads per slab. All GEMM K's divide by 16, so slabs never
// straddle a fold boundary.
// ---------------------------------------------------------------------------
__device__ __forceinline__ void gemm_body(
    const float* __restrict__ A, const float* __restrict__ B,
    const float* __restrict__ bias, const float* __restrict__ res,
    float* __restrict__ C, int M, int N, int K,
    float (&As)[2][16][128], float (&Bs)[2][16][64])
{
    int tid = threadIdx.x;
    int bm = blockIdx.y*128, bn = blockIdx.x*64;
    int tx = tid & 15, ty = tid >> 4;
    int lrow = tid >> 1, lcolA = (tid & 1)*8;      // A: 128 rows x 16 k, 2 float4/thread
    int lrB = tid >> 2, lcB = (tid & 3)*4;         // B: 64 rows x 16 k, 1 float4/thread
    bool aval = (bm+lrow) < M;
    bool bval = (bn+lrB) < N;
    const float* Ap = A + (size_t)(bm+lrow)*K + lcolA;
    const float* Bp = B + (size_t)(bn+lrB)*K + lcB;

    // preload slab 0
    float4 a0v = aval ? *(const float4*)(Ap)     : make_float4(0,0,0,0);
    float4 a1v = aval ? *(const float4*)(Ap + 4) : make_float4(0,0,0,0);
    float4 b0v = bval ? *(const float4*)(Bp)     : make_float4(0,0,0,0);
    As[0][lcolA+0][lrow]=a0v.x; As[0][lcolA+1][lrow]=a0v.y; As[0][lcolA+2][lrow]=a0v.z; As[0][lcolA+3][lrow]=a0v.w;
    As[0][lcolA+4][lrow]=a1v.x; As[0][lcolA+5][lrow]=a1v.y; As[0][lcolA+6][lrow]=a1v.z; As[0][lcolA+7][lrow]=a1v.w;
    Bs[0][lcB+0][lrB]=b0v.x; Bs[0][lcB+1][lrB]=b0v.y; Bs[0][lcB+2][lrB]=b0v.z; Bs[0][lcB+3][lrB]=b0v.w;
    __syncthreads();

    float blk[8][4], tot[8][4];
#pragma unroll
    for (int i=0;i<8;i++)
#pragma unroll
        for (int j=0;j<4;j++){ blk[i][j]=0.f; tot[i][j]=0.f; }

    int buf = 0;
    for (int k0=0;k0<K;k0+=16){
        bool hn = (k0+16) < K;
        float4 na0, na1, nb0;
        if (hn){
            na0 = aval ? *(const float4*)(Ap + k0 + 16) : make_float4(0,0,0,0);
            na1 = aval ? *(const float4*)(Ap + k0 + 20) : make_float4(0,0,0,0);
            nb0 = bval ? *(const float4*)(Bp + k0 + 16) : make_float4(0,0,0,0);
        }
#pragma unroll
        for (int kk=0;kk<16;kk++){
            float4 a0=*(const float4*)&As[buf][kk][ty*8];
            float4 a1=*(const float4*)&As[buf][kk][ty*8+4];
            float4 b0=*(const float4*)&Bs[buf][kk][tx*4];
            float av[8]={a0.x,a0.y,a0.z,a0.w,a1.x,a1.y,a1.z,a1.w};
            float bv[4]={b0.x,b0.y,b0.z,b0.w};
#pragma unroll
            for (int i=0;i<8;i++)
#pragma unroll
                for (int j=0;j<4;j++)
                    blk[i][j]=__fmaf_rn(av[i],bv[j],blk[i][j]);
        }
        int kn = k0 + 16;
        if ((kn % KC) == 0 || kn == K){   // Eigen fold boundary (16 | 768)
#pragma unroll
            for (int i=0;i<8;i++)
#pragma unroll
                for (int j=0;j<4;j++){ tot[i][j]=__fadd_rn(tot[i][j],blk[i][j]); blk[i][j]=0.f; }
        }
        if (hn){
            int nb = buf^1;
            As[nb][lcolA+0][lrow]=na0.x; As[nb][lcolA+1][lrow]=na0.y; As[nb][lcolA+2][lrow]=na0.z; As[nb][lcolA+3][lrow]=na0.w;
            As[nb][lcolA+4][lrow]=na1.x; As[nb][lcolA+5][lrow]=na1.y; As[nb][lcolA+6][lrow]=na1.z; As[nb][lcolA+7][lrow]=na1.w;
            Bs[nb][lcB+0][lrB]=nb0.x; Bs[nb][lcB+1][lrB]=nb0.y; Bs[nb][lcB+2][lrB]=nb0.z; Bs[nb][lcB+3][lrB]=nb0.w;
            __syncthreads();
            buf = nb;
        }
    }
#pragma unroll
    for (int i=0;i<8;i++){
        int r = bm + ty*8 + i;
        if (r < M){
#pragma unroll
            for (int j=0;j<4;j++){
                int c = bn + tx*4 + j;
                if (c < N){
                    float vv = tot[i][j];
                    if (res)  vv = __fadd_rn(res[(size_t)r*N+c], vv);
                    if (bias) vv = __fadd_rn(vv, bias[c]);
                    C[(size_t)r*N+c] = vv;
                }
            }
        }
    }
}

__global__ void __launch_bounds__(256,2) gemm_nt_kernel(
    const float* __restrict__ A, const float* __restrict__ B,
    const float* __restrict__ bias, const float* __restrict__ res,
    float* __restrict__ C, int M, int N, int K){
    __shared__ float As[2][16][128];
    __shared__ float Bs[2][16][64];
    gemm_body(A,B,bias,res,C,M,N,K,As,Bs);
}

// Fused Q/K/V: grid (12,16,3); z selects weight/bias/output
__global__ void __launch_bounds__(256,2) qkv_kernel(
    const float* __restrict__ h,
    const float* __restrict__ Wq, const float* __restrict__ Wk, const float* __restrict__ Wv,
    const float* __restrict__ bq, const float* __restrict__ bk, const float* __restrict__ bv,
    float* __restrict__ q, float* __restrict__ k, float* __restrict__ v){
    __shared__ float As[2][16][128];
    __shared__ float Bs[2][16][64];
    int z = blockIdx.z;
    const float* B  = (z==0) ? Wq : (z==1) ? Wk : Wv;
    const float* bi = (z==0) ? bq : (z==1) ? bk : bv;
    float*       C  = (z==0) ? q  : (z==1) ? k  : v;
    gemm_body(h,B,bi,nullptr,C,NTOK,DMODEL,DMODEL,As,Bs);
}

// scores: K=64 single ascending chain; *0.125 exact; -inf mask
__global__ void __launch_bounds__(256) attn_scores_kernel(
    const float* __restrict__ Q, const float* __restrict__ Kmat, float* __restrict__ att){
    int jt=blockIdx.x, it=blockIdx.y, bh=blockIdx.z;
    int b=bh/NHEAD, h=bh-b*NHEAD;
    int tid=threadIdx.x, tx=tid&15, ty=tid>>4;
    if (jt > it){
#pragma unroll
        for (int ii=0;ii<4;ii++)
#pragma unroll
            for (int jj=0;jj<4;jj++){
                int i=it*64+ty*4+ii, j=jt*64+tx*4+jj;
                att[((size_t)bh*SEQ+i)*SEQ+j] = -INFINITY;
            }
        return;
    }
    __shared__ float qs[16][64];
    __shared__ float ks[16][64];
    float acc[4][4]={};
    int lr=tid>>2, lc=(tid&3)*4;
    const float* qb = Q    + ((size_t)(b*SEQ+it*64+lr))*DMODEL + h*HDIM;
    const float* kb = Kmat + ((size_t)(b*SEQ+jt*64+lr))*DMODEL + h*HDIM;
    for (int d0=0;d0<HDIM;d0+=16){
        float4 qv=*(const float4*)(qb+d0+lc);
        float4 kv=*(const float4*)(kb+d0+lc);
        qs[lc+0][lr]=qv.x; qs[lc+1][lr]=qv.y; qs[lc+2][lr]=qv.z; qs[lc+3][lr]=qv.w;
        ks[lc+0][lr]=kv.x; ks[lc+1][lr]=kv.y; ks[lc+2][lr]=kv.z; ks[lc+3][lr]=kv.w;
        __syncthreads();
#pragma unroll
        for (int kk=0;kk<16;kk++){
            float4 a=*(const float4*)&qs[kk][ty*4];
            float4 c=*(const float4*)&ks[kk][tx*4];
            float av[4]={a.x,a.y,a.z,a.w}, cv[4]={c.x,c.y,c.z,c.w};
#pragma unroll
            for (int ii=0;ii<4;ii++)
#pragma unroll
                for (int jj=0;jj<4;jj++)
                    acc[ii][jj]=__fmaf_rn(av[ii],cv[jj],acc[ii][jj]);
        }
        __syncthreads();
    }
#pragma unroll
    for (int ii=0;ii<4;ii++)
#pragma unroll
        for (int jj=0;jj<4;jj++){
            int i=it*64+ty*4+ii, j=jt*64+tx*4+jj;
            att[((size_t)bh*SEQ+i)*SEQ+j] = (j<=i) ? __fmul_rn(acc[ii][jj],0.125f) : -INFINITY;
        }
}

// softmax: tree max (order-exact), XLA exp, sequential sum, true division
__global__ void __launch_bounds__(256) softmax_seq_kernel(float* __restrict__ att){
    __shared__ float e[SEQ];
    __shared__ float red[256];
    __shared__ float s_sum;
    int r=blockIdx.x, t=threadIdx.x;
    float* rowp = att + (size_t)r*SEQ;
    float a=rowp[t], b=rowp[t+256];
    red[t]=fmaxf(a,b);
    __syncthreads();
    for (int s=128;s>0;s>>=1){ if (t<s) red[t]=fmaxf(red[t],red[t+s]); __syncthreads(); }
    float m = red[0];
    e[t]     = xla_expf(__fsub_rn(a,m));
    e[t+256] = xla_expf(__fsub_rn(b,m));
    __syncthreads();
    if (t==0){
        float s=0.f;
        for (int i=0;i<SEQ;i++) s=__fadd_rn(s,e[i]);
        s_sum=s;
    }
    __syncthreads();
    float s=s_sum;
    rowp[t]     = __fdiv_rn(e[t],s);
    rowp[t+256] = __fdiv_rn(e[t+256],s);
}

// y = att @ v : K<=512 -> single ascending chain
__global__ void __launch_bounds__(256) attn_av_kernel(
    const float* __restrict__ att, const float* __restrict__ V, float* __restrict__ Y){
    int it=blockIdx.x, bh=blockIdx.y;
    int b=bh/NHEAD, h=bh-b*NHEAD;
    int tid=threadIdx.x, tx=tid&15, ty=tid>>4;
    __shared__ float as_s[16][64];
    __shared__ float vs_s[16][64];
    float acc[4][4]={};
    int ar=tid>>2, ac4=(tid&3)*4;
    int vr=tid>>4, vc4=(tid&15)*4;
    int jmax=(it+1)*64;
    for (int j0=0;j0<jmax;j0+=16){
        float4 av=*(const float4*)(att + ((size_t)bh*SEQ+it*64+ar)*SEQ + j0 + ac4);
        as_s[ac4+0][ar]=av.x; as_s[ac4+1][ar]=av.y; as_s[ac4+2][ar]=av.z; as_s[ac4+3][ar]=av.w;
        float4 vv=*(const float4*)(V + ((size_t)(b*SEQ+j0+vr))*DMODEL + h*HDIM + vc4);
        *(float4*)&vs_s[vr][vc4]=vv;
        __syncthreads();
#pragma unroll
        for (int jj=0;jj<16;jj++){
            float4 a=*(const float4*)&as_s[jj][ty*4];
            float4 c=*(const float4*)&vs_s[jj][tx*4];
            float av2[4]={a.x,a.y,a.z,a.w}, cv[4]={c.x,c.y,c.z,c.w};
#pragma unroll
            for (int ii=0;ii<4;ii++)
#pragma unroll
                for (int dd=0;dd<4;dd++)
                    acc[ii][dd]=__fmaf_rn(av2[ii],cv[dd],acc[ii][dd]);
        }
        __syncthreads();
    }
#pragma unroll
    for (int ii=0;ii<4;ii++)
#pragma unroll
        for (int dd=0;dd<4;dd++)
            Y[((size_t)(b*SEQ+it*64+ty*4+ii))*DMODEL + h*HDIM + tx*4 + dd] = acc[ii][dd];
}

__device__ __forceinline__ unsigned fkey(float f){
    unsigned b=__float_as_uint(f);
    return (b & 0x80000000u) ? ~b : (b | 0x80000000u);
}
__device__ __forceinline__ float fromkey(unsigned u){
    unsigned b=(u & 0x80000000u) ? (u & 0x7fffffffu) : ~u;
    return __uint_as_float(b);
}

template <int ROW, bool GELU, bool RESID>
__global__ void __launch_bounds__(256) kwinners_kernel(
    const float* __restrict__ Z, float* __restrict__ out, int kcount){
    __shared__ float vals[ROW];
    __shared__ unsigned hist[256];
    __shared__ unsigned s_prefix;
    __shared__ int s_k;
    int row=blockIdx.x, tid=threadIdx.x;
    const float* zr = Z + (size_t)row*ROW;
    for (int i=tid;i<ROW;i+=256) vals[i]=zr[i];
    if (tid==0){ s_prefix=0u; s_k=kcount; }
    __syncthreads();
    for (int pass=0;pass<4;pass++){
        int shift=24-8*pass;
        hist[tid]=0u;
        __syncthreads();
        unsigned pfx=s_prefix;
        for (int i=tid;i<ROW;i+=256){
            unsigned u=fkey(vals[i]);
            if (pass==0 || (u>>(shift+8))==pfx) atomicAdd(&hist[(u>>shift)&255u],1u);
        }
        __syncthreads();
        if (tid==0){
            int kk=s_k; unsigned p=pfx;
            for (int bb=255;bb>=0;bb--){
                int c=(int)hist[bb];
                if (kk<=c){ p=(p<<8)|(unsigned)bb; break; }
                kk-=c;
            }
            s_prefix=p; s_k=kk;
        }
        __syncthreads();
    }
    float thr=fromkey(s_prefix);
    float* o = out + (size_t)row*ROW;
    for (int i=tid;i<ROW;i+=256){
        float v=vals[i];
        if (GELU){
            o[i] = (v>=thr) ? gelu_ref(v) : 0.0f;
        } else if (RESID){
            o[i] = __fadd_rn(o[i], (v>=thr)?v:0.0f);
        } else {
            o[i] = (v>=thr)?v:0.0f;
        }
    }
}

__global__ void copy_kernel(const float* __restrict__ src, float* __restrict__ dst, int n){
    int i=blockIdx.x*blockDim.x+threadIdx.x;
    if (i<n) dst[i]=src[i];
}

extern "C" void kernel_launch(void* const* d_in, const int* in_sizes, int n_in,
                              void* d_out, int out_size){
    const int*   idx  = (const int*)  d_in[0];
    const float* tok  = (const float*)d_in[1];
    const float* pos  = (const float*)d_in[2];
    const float* ln1s = (const float*)d_in[3];
    const float* ln1b = (const float*)d_in[4];
    const float* Wq   = (const float*)d_in[5];
    const float* bq   = (const float*)d_in[6];
    const float* Wk   = (const float*)d_in[7];
    const float* bk   = (const float*)d_in[8];
    const float* Wv   = (const float*)d_in[9];
    const float* bv   = (const float*)d_in[10];
    const float* Wp   = (const float*)d_in[11];
    const float* bp   = (const float*)d_in[12];
    const float* ln2s = (const float*)d_in[13];
    const float* ln2b = (const float*)d_in[14];
    const float* W1   = (const float*)d_in[15];
    const float* b1   = (const float*)d_in[16];
    const float* W2   = (const float*)d_in[17];
    const float* b2   = (const float*)d_in[18];
    const float* lnfs = (const float*)d_in[19];
    const float* lnfb = (const float*)d_in[20];
    const float* headW= (const float*)d_in[21];
    float* out = (float*)d_out;

    float *x,*h,*q,*k,*v,*y,*z,*att,*z1;
    cudaGetSymbolAddress((void**)&x,g_x);
    cudaGetSymbolAddress((void**)&h,g_h);
    cudaGetSymbolAddress((void**)&q,g_q);
    cudaGetSymbolAddress((void**)&k,g_k);
    cudaGetSymbolAddress((void**)&v,g_v);
    cudaGetSymbolAddress((void**)&y,g_y);
    cudaGetSymbolAddress((void**)&z,g_z);
    cudaGetSymbolAddress((void**)&att,g_att);
    cudaGetSymbolAddress((void**)&z1,g_z1);

    embed_kernel<<<(NTOK*DMODEL+255)/256,256>>>(idx,tok,pos,x);

    dim3 gD(DMODEL/64, NTOK/128);             // (12,16)
    dim3 gQKV(DMODEL/64, NTOK/128, 3);        // (12,16,3)
    dim3 gF(FFDIM/64, NTOK/128);              // (48,16)
    dim3 gS(SEQ/64, SEQ/64, NBATCH*NHEAD);
    dim3 gA(SEQ/64, NBATCH*NHEAD);

    for (int l=0;l<NLAYER;l++){
        size_t wo  = (size_t)l*DMODEL*DMODEL;
        size_t wo1 = (size_t)l*FFDIM*DMODEL;
        ln_seq_kernel<<<NTOK,256>>>(x, ln1s+l*DMODEL, ln1b+l*DMODEL, h);
        qkv_kernel<<<gQKV,256>>>(h, Wq+wo, Wk+wo, Wv+wo,
                                 bq+l*DMODEL, bk+l*DMODEL, bv+l*DMODEL, q, k, v);
        attn_scores_kernel<<<gS,256>>>(q, k, att);
        softmax_seq_kernel<<<NBATCH*NHEAD*SEQ,256>>>(att);
        attn_av_kernel<<<gA,256>>>(att, v, y);
        gemm_nt_kernel<<<gD,256>>>(y, Wp+wo, bp+l*DMODEL, x, x, NTOK, DMODEL, DMODEL);
        ln_seq_kernel<<<NTOK,256>>>(x, ln2s+l*DMODEL, ln2b+l*DMODEL, h);
        gemm_nt_kernel<<<gF,256>>>(h, W1+wo1, b1+l*FFDIM, nullptr, z1, NTOK, FFDIM, DMODEL);
        kwinners_kernel<FFDIM,true,false><<<NTOK,256>>>(z1, z1, K1W);
        gemm_nt_kernel<<<gD,256>>>(z1, W2+wo1, b2+l*DMODEL, nullptr, h, NTOK, DMODEL, FFDIM);
        kwinners_kernel<DMODEL,false,true><<<NTOK,256>>>(h, x, K2W);
    }

    ln_seq_kernel<<<NTOK,256>>>(x, lnfs, lnfb, z);
    dim3 gH((VOCAB+63)/64, NTOK/128);         // (786,16)
    gemm_nt_kernel<<<gH,256>>>(z, headW, nullptr, nullptr, out, NTOK, VOCAB, DMODEL);

    size_t zoff = (size_t)NTOK*VOCAB;
    if ((size_t)out_size >= zoff + (size_t)NTOK*DMODEL)
        copy_kernel<<<(NTOK*DMODEL+255)/256,256>>>(z, out+zoff, NTOK*DMODEL);
}